// round 6
// baseline (speedup 1.0000x reference)
#include <cuda_runtime.h>
#include <cuda_bf16.h>
#include <cuda_fp8.h>
#include <cstdint>

#define BPAIRS 4096
#define NROWS  8192
#define DCOLS  256

#define TL 64                  // tile grid dim (8192/128)
#define NT 2080                // TL*(TL+1)/2
#define GRID 296               // persistent CTAs

#define SKB 272                // padded smem row stride (bytes)
#define A_BYTES (128 * SKB)    // 34816: full A tile (128 rows)
#define BH_BYTES (64 * SKB)    // 17408: half B tile (64 rows)
#define A_OFF  0
#define B0_OFF A_BYTES
#define B1_OFF (A_BYTES + BH_BYTES)
#define SMEM_TOTAL (A_BYTES + 2 * BH_BYTES)   // 69632

#define QSCALE 16.0f           // g_fp8 = 256 * g_true
#define C1 (4.0f / 256.0f * 1.4426950408889634f)
#define C2 (4.0f * 1.4426950408889634f)

__device__ __align__(16) uint8_t g_X[NROWS * DCOLS];   // e4m3, scaled by 16
__device__ float g_align[BPAIRS];
__device__ float g_uni[GRID];
__device__ unsigned int g_done;

__device__ __forceinline__ uint32_t smem_u32(const void* p) {
    uint32_t a;
    asm("{ .reg .u64 t; cvta.to.shared.u64 t, %1; cvt.u32.u64 %0, t; }" : "=r"(a) : "l"(p));
    return a;
}
__device__ __forceinline__ void qmma(float d[4], const uint32_t a[4], uint32_t b0, uint32_t b1) {
    asm volatile(
        "mma.sync.aligned.m16n8k32.row.col.f32.e4m3.e4m3.f32 "
        "{%0,%1,%2,%3}, {%4,%5,%6,%7}, {%8,%9}, {%0,%1,%2,%3};\n"
        : "+f"(d[0]), "+f"(d[1]), "+f"(d[2]), "+f"(d[3])
        : "r"(a[0]), "r"(a[1]), "r"(a[2]), "r"(a[3]), "r"(b0), "r"(b1));
}
__device__ __forceinline__ void ldsm4(uint32_t r[4], uint32_t addr) {
    asm volatile("ldmatrix.sync.aligned.m8n8.x4.shared.b16 {%0,%1,%2,%3}, [%4];"
                 : "=r"(r[0]), "=r"(r[1]), "=r"(r[2]), "=r"(r[3]) : "r"(addr));
}
__device__ __forceinline__ void cpasync16(uint32_t dst, const void* src) {
    asm volatile("cp.async.cg.shared.global [%0], [%1], 16;" :: "r"(dst), "l"(src));
}
__device__ __forceinline__ float ex2(float x) {
    float r;
    asm("ex2.approx.ftz.f32 %0, %1;" : "=f"(r) : "f"(x));
    return r;
}

__global__ void k_norm(const float* __restrict__ A, const float* __restrict__ B) {
    int r = blockIdx.x;
    int t = threadIdx.x;           // 256 == DCOLS
    if (r == 0 && t == 0) g_done = 0u;
    float a = A[r * DCOLS + t];
    float b = B[r * DCOLS + t];
    float sa = a * a, sb = b * b;
    #pragma unroll
    for (int o = 16; o; o >>= 1) {
        sa += __shfl_xor_sync(0xffffffffu, sa, o);
        sb += __shfl_xor_sync(0xffffffffu, sb, o);
    }
    __shared__ float ssa[8], ssb[8], sdd[8];
    int wid = t >> 5, lane = t & 31;
    if (lane == 0) { ssa[wid] = sa; ssb[wid] = sb; }
    __syncthreads();
    float na = 0.f, nb = 0.f;
    #pragma unroll
    for (int i = 0; i < 8; i++) { na += ssa[i]; nb += ssb[i]; }
    na = fmaxf(sqrtf(na), 1e-12f);
    nb = fmaxf(sqrtf(nb), 1e-12f);
    float an = a / na, bn = b / nb;
    g_X[r * DCOLS + t] =
        (uint8_t)__nv_cvt_float_to_fp8(an * QSCALE, __NV_SATFINITE, __NV_E4M3);
    g_X[(BPAIRS + r) * DCOLS + t] =
        (uint8_t)__nv_cvt_float_to_fp8(bn * QSCALE, __NV_SATFINITE, __NV_E4M3);
    float d = an - bn;
    float dd = d * d;
    #pragma unroll
    for (int o = 16; o; o >>= 1) dd += __shfl_xor_sync(0xffffffffu, dd, o);
    if (lane == 0) sdd[wid] = dd;
    __syncthreads();
    if (t == 0) {
        float s = 0.f;
        #pragma unroll
        for (int i = 0; i < 8; i++) s += sdd[i];
        g_align[r] = s;
    }
}

// Persistent fp8 Gram, 3 CTAs/SM. Each 128x128 tile = two 128x64 passes;
// B staged in 64-row halves (2-slot ring, prefetched 1 unit ahead); A resident
// per tile-row. Warp tile 32x32 -> 32-reg accumulator.
__global__ __launch_bounds__(256, 3) void k_gram(float* __restrict__ out) {
    extern __shared__ __align__(128) char smem[];
    __shared__ float sred[16];
    __shared__ int sflag[1];
    uint32_t sb = smem_u32(smem);

    int tid = threadIdx.x;
    int wid = tid >> 5, lane = tid & 31;
    int m0 = (wid >> 1) * 32;          // 4 row groups
    int n0 = (wid & 1) * 32;           // 2 col groups (within 64-col pass)
    int cta = blockIdx.x;

    int lo = (int)(((long long)cta * NT) / GRID);
    int hi = (int)(((long long)(cta + 1) * NT) / GRID);

    // decode lo -> (bi, bj)
    int bi = 0, rem = lo, rl = TL;
    while (rem >= rl) { rem -= rl; bi++; rl--; }
    int bj = bi + rem;

    // fragment offsets
    uint32_t a_off = (uint32_t)((m0 + (lane & 15)) * SKB + ((lane >> 4) << 4));
    int bcol = (lane & 7) + ((lane >> 4) << 3);        // 0..15
    uint32_t b_off = (uint32_t)((n0 + bcol) * SKB + ((lane & 8) ? 16 : 0));

    // staging lane coords: 16 threads per 256B row
    int srow = tid >> 4, scol = (tid & 15) << 4;

    // stage A tile: 128 rows
    auto stage_a = [&](int row128) {
        const uint8_t* g = &g_X[(size_t)row128 * 128 * DCOLS + scol];
        uint32_t d = sb + A_OFF + (uint32_t)(srow * SKB) + (uint32_t)scol;
        #pragma unroll
        for (int i = 0; i < 8; i++)
            cpasync16(d + i * 16 * SKB, g + (size_t)(i * 16) * DCOLS + (size_t)srow * DCOLS);
    };
    // stage 64-row B half into slot
    auto stage_bh = [&](int slot, int tile_bj, int half) {
        const uint8_t* g = &g_X[((size_t)tile_bj * 128 + half * 64) * DCOLS + scol];
        uint32_t d = sb + (slot ? B1_OFF : B0_OFF) + (uint32_t)(srow * SKB) + (uint32_t)scol;
        #pragma unroll
        for (int i = 0; i < 4; i++)
            cpasync16(d + i * 16 * SKB, g + (size_t)(i * 16) * DCOLS + (size_t)srow * DCOLS);
    };

    float srun = 0.0f;
    int ulo = 2 * lo, uhi = 2 * hi;

    // prologue: A(bi), B(bj, half 0) into slot 0  (ulo is even -> slot 0)
    stage_a(bi);
    stage_bh(0, bj, 0);
    asm volatile("cp.async.commit_group;" ::: "memory");

    for (int u = ulo; u < uhi; u++) {
        int slot = u & 1;                 // == pass index
        asm volatile("cp.async.wait_group 0;" ::: "memory");
        __syncthreads();

        // next unit coords
        bool has_next = (u + 1 < uhi);
        int np = (u + 1) & 1;
        int nbi = bi, nbj = bj;
        if (np == 0) { nbj = bj + 1; if (nbj >= TL) { nbi = bi + 1; nbj = nbi; } }
        bool rowchg = (np == 0) && (nbi != bi);

        if (has_next && !rowchg) {
            stage_bh(np, nbj, np);
            asm volatile("cp.async.commit_group;" ::: "memory");
        }

        uint32_t abase = sb + A_OFF + a_off;
        uint32_t bbase = sb + (slot ? B1_OFF : B0_OFF) + b_off;

        float acc[2][4][4];
        #pragma unroll
        for (int mi = 0; mi < 2; mi++)
            #pragma unroll
            for (int ni = 0; ni < 4; ni++)
                #pragma unroll
                for (int e = 0; e < 4; e++) acc[mi][ni][e] = 0.0f;

        #pragma unroll
        for (int ks = 0; ks < DCOLS / 32; ks++) {
            uint32_t a0[4], a1[4], bl[4], bh[4];
            ldsm4(a0, abase + ks * 32);
            ldsm4(a1, abase + 16 * SKB + ks * 32);
            ldsm4(bl, bbase + ks * 32);
            ldsm4(bh, bbase + 16 * SKB + ks * 32);
            qmma(acc[0][0], a0, bl[0], bl[1]);
            qmma(acc[0][1], a0, bl[2], bl[3]);
            qmma(acc[1][0], a1, bl[0], bl[1]);
            qmma(acc[1][1], a1, bl[2], bl[3]);
            qmma(acc[0][2], a0, bh[0], bh[1]);
            qmma(acc[0][3], a0, bh[2], bh[3]);
            qmma(acc[1][2], a1, bh[0], bh[1]);
            qmma(acc[1][3], a1, bh[2], bh[3]);
        }

        float s = 0.0f;
        #pragma unroll
        for (int mi = 0; mi < 2; mi++)
            #pragma unroll
            for (int ni = 0; ni < 4; ni++)
                #pragma unroll
                for (int e = 0; e < 4; e++) {
                    float tt = fminf(acc[mi][ni][e] * C1 - C2, 0.0f);
                    s += ex2(tt);
                }
        srun += (bi == bj) ? s : 2.0f * s;

        if (has_next && rowchg) {
            __syncthreads();   // all warps done with A before overwrite
            stage_a(nbi);
            stage_bh(np, nbj, np);
            asm volatile("cp.async.commit_group;" ::: "memory");
        }
        bi = nbi; bj = nbj;
    }

    // per-CTA reduction -> g_uni[cta]
    #pragma unroll
    for (int o = 16; o; o >>= 1) srun += __shfl_xor_sync(0xffffffffu, srun, o);
    if (lane == 0) sred[wid] = srun;
    __syncthreads();
    if (tid == 0) {
        float tot = 0.f;
        #pragma unroll
        for (int i = 0; i < 8; i++) tot += sred[i];
        g_uni[cta] = tot;
        __threadfence();
        unsigned int prev = atomicAdd(&g_done, 1u);
        sflag[0] = (prev == GRID - 1) ? 1 : 0;
    }
    __syncthreads();

    // last CTA finalizes
    if (sflag[0]) {
        float sa = 0.f, su = 0.f;
        for (int i = tid; i < BPAIRS; i += 256) sa += g_align[i];
        for (int i = tid; i < GRID; i += 256) su += g_uni[i];
        #pragma unroll
        for (int o = 16; o; o >>= 1) {
            sa += __shfl_xor_sync(0xffffffffu, sa, o);
            su += __shfl_xor_sync(0xffffffffu, su, o);
        }
        if (lane == 0) { sred[wid] = sa; sred[wid + 8] = su; }
        __syncthreads();
        if (tid == 0) {
            float ta = 0.f, tu = 0.f;
            #pragma unroll
            for (int i = 0; i < 8; i++) { ta += sred[i]; tu += sred[i + 8]; }
            float align_loss = ta / (float)BPAIRS;
            float uniform_loss = (tu - (float)NROWS) / ((float)NROWS * (float)(NROWS - 1));
            out[0] = align_loss + uniform_loss;
        }
    }
}

extern "C" void kernel_launch(void* const* d_in, const int* in_sizes, int n_in,
                              void* d_out, int out_size) {
    const float* A = (const float*)d_in[0];
    const float* B = (const float*)d_in[1];
    float* out = (float*)d_out;

    cudaFuncSetAttribute(k_gram, cudaFuncAttributeMaxDynamicSharedMemorySize, SMEM_TOTAL);

    k_norm<<<BPAIRS, 256>>>(A, B);
    k_gram<<<GRID, 256, SMEM_TOTAL>>>(out);
}